// round 1
// baseline (speedup 1.0000x reference)
#include <cuda_runtime.h>
#include <math.h>

#define NN 50000
#define NE 800000
#define NF 256
#define NH 64
#define NC 16

// ---------------- static scratch (no allocations allowed) ----------------
__device__ __align__(256) float g_Z [NN * 192];   // GEMM input/output staging
__device__ __align__(256) float g_h [NN * NH];    // h = tanh(conv1(x))
__device__ __align__(256) float g_y [NN * NH];    // RK4 stage input
__device__ __align__(256) float g_t [NN * NH];    // intermediate inside f()
__device__ __align__(256) float g_k [NN * NH];    // current k_i
__device__ __align__(256) float g_ka[NN * NH];    // k accumulator
__device__ __align__(256) float g_hf[NN * NH];    // final h
__device__ __align__(256) float g_G2[NN * 48];    // conv2 transform output
__device__ __align__(256) float g_B1[NF * 192];   // [W1_0 | W1_1-W1_0 | R1]
__device__ __align__(256) float g_BA[192 * NH];   // [Wa_0; Wa_1-Wa_0; Ra]
__device__ __align__(256) float g_BB[192 * NH];
__device__ __align__(256) float g_B2[NH * 48];    // [W2_0 | W2_1-W2_0 | R2]
__device__ int   g_rp[NN + 1];
__device__ int   g_wp[NN];
__device__ int   g_cnt[NN];
__device__ float g_invd[NN];
__device__ int   g_esrc[NE];
__device__ __align__(256) float g_ep[NE];

// ---------------- CSR build ----------------
__global__ void k_zero() {
    int i = blockIdx.x * blockDim.x + threadIdx.x;
    if (i < NN) g_cnt[i] = 0;
}

__global__ void k_hist(const int* __restrict__ dst) {
    int e = blockIdx.x * blockDim.x + threadIdx.x;
    if (e < NE) atomicAdd(&g_cnt[dst[e]], 1);
}

// single-block exclusive scan over 50k counts; also writes write-ptrs and 1/deg
__global__ void k_scan() {
    __shared__ int wsum[32];
    __shared__ int carry_s;
    int tid = threadIdx.x, lane = tid & 31, wid = tid >> 5;
    if (tid == 0) carry_s = 0;
    __syncthreads();
    for (int base = 0; base < NN; base += 1024) {
        int i = base + tid;
        int v = (i < NN) ? g_cnt[i] : 0;
        int x = v;
        #pragma unroll
        for (int off = 1; off < 32; off <<= 1) {
            int t = __shfl_up_sync(0xffffffffu, x, off);
            if (lane >= off) x += t;
        }
        if (lane == 31) wsum[wid] = x;
        __syncthreads();
        if (wid == 0) {
            int s = wsum[lane];
            #pragma unroll
            for (int off = 1; off < 32; off <<= 1) {
                int t = __shfl_up_sync(0xffffffffu, s, off);
                if (lane >= off) s += t;
            }
            wsum[lane] = s;
        }
        __syncthreads();
        int excl = carry_s + (wid > 0 ? wsum[wid - 1] : 0) + x - v;
        if (i < NN) {
            g_rp[i]  = excl;
            g_wp[i]  = excl;
            g_invd[i] = 1.0f / (float)(v > 0 ? v : 1);
        }
        __syncthreads();
        if (tid == 0) carry_s += wsum[31];
        __syncthreads();
    }
    if (threadIdx.x == 0) g_rp[NN] = carry_s;
}

__global__ void k_scatter(const int* __restrict__ src, const int* __restrict__ dst,
                          const float* __restrict__ p) {
    int e = blockIdx.x * blockDim.x + threadIdx.x;
    if (e < NE) {
        int d   = dst[e];
        int pos = atomicAdd(&g_wp[d], 1);
        g_esrc[pos] = src[e];
        g_ep[pos]   = p[e];
    }
}

// ---------------- weight prep ----------------
// transform-first: B[Cin][3*Cout] cols = [W0 | W1-W0 | R]
__global__ void k_prep_tf(const float* __restrict__ W, const float* __restrict__ R,
                          float* __restrict__ B, int Cin, int Cout) {
    int i = blockIdx.x * blockDim.x + threadIdx.x;
    int tot = Cin * 3 * Cout;
    if (i >= tot) return;
    int r = i / (3 * Cout), c = i % (3 * Cout);
    float v;
    if (c < Cout)            v = W[r * Cout + c];
    else if (c < 2 * Cout)   v = W[Cin * Cout + r * Cout + (c - Cout)] - W[r * Cout + (c - Cout)];
    else                     v = R[r * Cout + (c - 2 * Cout)];
    B[i] = v;
}

// aggregate-first: B[3C][C] rows = [W0; W1-W0; R]
__global__ void k_prep_af(const float* __restrict__ W, const float* __restrict__ R,
                          float* __restrict__ B, int C) {
    int i = blockIdx.x * blockDim.x + threadIdx.x;
    int tot = 3 * C * C;
    if (i >= tot) return;
    int r = i / C, c = i % C;
    float v;
    if (r < C)          v = W[r * C + c];
    else if (r < 2 * C) v = W[C * C + (r - C) * C + c] - W[(r - C) * C + c];
    else                v = R[(r - 2 * C) * C + c];
    B[i] = v;
}

// ---------------- GEMM: C[M,N] = A[M,K] @ B[K,N] (+bias) (+RK4 epilogue) ----------------
// 128x64 block tile, 128 threads, 8x8 per thread, BK=16. K must be a multiple of 16.
__global__ void __launch_bounds__(128) k_gemm(
    const float* __restrict__ A, const float* __restrict__ B,
    float* __restrict__ C, const float* __restrict__ bias,
    int M, int K, int N, int ldc,
    int mode, const float* __restrict__ hin, float* __restrict__ ynext,
    float* __restrict__ kacc, float ccoef, float wcoef, int kinit)
{
    __shared__ float As[16][128];
    __shared__ float Bs[16][64];
    int tid = threadIdx.x;
    int bm = blockIdx.x * 128;
    int bn = blockIdx.y * 64;
    int trow = (tid >> 3) * 8;   // 0..120
    int tcol = (tid & 7) * 8;    // 0..56

    float acc[8][8];
    #pragma unroll
    for (int i = 0; i < 8; i++)
        #pragma unroll
        for (int j = 0; j < 8; j++) acc[i][j] = 0.0f;

    for (int k0 = 0; k0 < K; k0 += 16) {
        // A tile: 128x16 = 512 float4, 4 per thread
        #pragma unroll
        for (int q = 0; q < 4; q++) {
            int l = q * 128 + tid;
            int m = l >> 2;
            int kk = (l & 3) * 4;
            int gr = bm + m;
            float4 av = make_float4(0.f, 0.f, 0.f, 0.f);
            if (gr < M) av = *(const float4*)(A + (size_t)gr * K + k0 + kk);
            As[kk + 0][m] = av.x; As[kk + 1][m] = av.y;
            As[kk + 2][m] = av.z; As[kk + 3][m] = av.w;
        }
        // B tile: 16x64 = 256 float4, 2 per thread (guard cols for N<64)
        #pragma unroll
        for (int q = 0; q < 2; q++) {
            int l = q * 128 + tid;
            int br = l >> 4;
            int bc = (l & 15) * 4;
            int gc = bn + bc;
            float4 bv;
            if (gc + 3 < N) {
                bv = *(const float4*)(B + (size_t)(k0 + br) * N + gc);
            } else {
                bv.x = (gc + 0 < N) ? B[(size_t)(k0 + br) * N + gc + 0] : 0.f;
                bv.y = (gc + 1 < N) ? B[(size_t)(k0 + br) * N + gc + 1] : 0.f;
                bv.z = (gc + 2 < N) ? B[(size_t)(k0 + br) * N + gc + 2] : 0.f;
                bv.w = (gc + 3 < N) ? B[(size_t)(k0 + br) * N + gc + 3] : 0.f;
            }
            *(float4*)&Bs[br][bc] = bv;
        }
        __syncthreads();
        #pragma unroll
        for (int kk = 0; kk < 16; kk++) {
            float4 a0 = *(const float4*)&As[kk][trow];
            float4 a1 = *(const float4*)&As[kk][trow + 4];
            float4 b0 = *(const float4*)&Bs[kk][tcol];
            float4 b1 = *(const float4*)&Bs[kk][tcol + 4];
            float a[8] = {a0.x, a0.y, a0.z, a0.w, a1.x, a1.y, a1.z, a1.w};
            float b[8] = {b0.x, b0.y, b0.z, b0.w, b1.x, b1.y, b1.z, b1.w};
            #pragma unroll
            for (int i = 0; i < 8; i++)
                #pragma unroll
                for (int j = 0; j < 8; j++)
                    acc[i][j] += a[i] * b[j];
        }
        __syncthreads();
    }

    #pragma unroll
    for (int i = 0; i < 8; i++) {
        int r = bm + trow + i;
        if (r >= M) continue;
        #pragma unroll
        for (int j = 0; j < 8; j++) {
            int gc = bn + tcol + j;
            if (gc >= N) continue;
            float v = acc[i][j];
            if (bias) v += bias[gc];
            C[(size_t)r * ldc + gc] = v;
            if (mode) {
                size_t ei = (size_t)r * 64 + gc;   // mode only used when N==64
                if (ynext) ynext[ei] = hin[ei] + ccoef * v;
                kacc[ei] = kinit ? wcoef * v : kacc[ei] + wcoef * v;
            }
        }
    }
}

// ---------------- edge kernels (CSR, warp per node) ----------------
// aggregate-first: Z[v] = [invd*sum x_src | invd*sum p*x_src | x_v]
__global__ void k_agg(const float* __restrict__ yin) {
    int warp = (blockIdx.x * blockDim.x + threadIdx.x) >> 5;
    if (warp >= NN) return;
    int v = warp, lane = threadIdx.x & 31, c = lane * 2;
    float a0x = 0.f, a0y = 0.f, a1x = 0.f, a1y = 0.f;
    int s = g_rp[v], e = g_rp[v + 1];
    for (int i = s; i < e; i++) {
        int u = g_esrc[i];
        float p = g_ep[i];
        float2 xv = *(const float2*)(yin + (size_t)u * 64 + c);
        a0x += xv.x; a0y += xv.y;
        a1x += p * xv.x; a1y += p * xv.y;
    }
    float id = g_invd[v];
    float2 yv = *(const float2*)(yin + (size_t)v * 64 + c);
    float* row = g_Z + (size_t)v * 192;
    *(float2*)(row + c)        = make_float2(a0x * id, a0y * id);
    *(float2*)(row + 64 + c)   = make_float2(a1x * id, a1y * id);
    *(float2*)(row + 128 + c)  = yv;
}

// conv1 edge pass (transform-first, Cout=64) + bias + tanh -> g_h
__global__ void k_edge1(const float* __restrict__ b1) {
    int warp = (blockIdx.x * blockDim.x + threadIdx.x) >> 5;
    if (warp >= NN) return;
    int v = warp, lane = threadIdx.x & 31, c = lane * 2;
    float a0 = 0.f, a1 = 0.f;
    int s = g_rp[v], e = g_rp[v + 1];
    for (int i = s; i < e; i++) {
        int u = g_esrc[i];
        float p = g_ep[i];
        const float* zr = g_Z + (size_t)u * 192;
        float2 y0 = *(const float2*)(zr + c);
        float2 y1 = *(const float2*)(zr + 64 + c);
        a0 += y0.x + p * y1.x;
        a1 += y0.y + p * y1.y;
    }
    float id = g_invd[v];
    const float* zv = g_Z + (size_t)v * 192 + 128;
    float o0 = tanhf(a0 * id + zv[c]     + b1[c]);
    float o1 = tanhf(a1 * id + zv[c + 1] + b1[c + 1]);
    *(float2*)(g_h + (size_t)v * 64 + c) = make_float2(o0, o1);
}

// hf = h + 0.5*kacc
__global__ void k_comb() {
    int i = blockIdx.x * blockDim.x + threadIdx.x;
    if (i < NN * NH) g_hf[i] = g_h[i] + 0.5f * g_ka[i];
}

// conv2 edge pass (transform-first, Cout=16) + bias + tanh + log_softmax
__global__ void k_edge2(const float* __restrict__ b2, float* __restrict__ out) {
    int warp = (blockIdx.x * blockDim.x + threadIdx.x) >> 5;
    if (warp >= NN) return;
    int v = warp, lane = threadIdx.x & 31, c = lane & 15;
    float a = 0.f;
    int s = g_rp[v], e = g_rp[v + 1];
    for (int i = s; i < e; i++) {
        int u = g_esrc[i];
        float p = g_ep[i];
        const float* gr = g_G2 + (size_t)u * 48;
        a += gr[c] + p * gr[16 + c];
    }
    float id = g_invd[v];
    float val = tanhf(a * id + g_G2[(size_t)v * 48 + 32 + c] + b2[c]);
    float m = val;
    #pragma unroll
    for (int off = 8; off; off >>= 1)
        m = fmaxf(m, __shfl_xor_sync(0xffffffffu, m, off, 16));
    float ex = expf(val - m);
    float ssum = ex;
    #pragma unroll
    for (int off = 8; off; off >>= 1)
        ssum += __shfl_xor_sync(0xffffffffu, ssum, off, 16);
    if (lane < 16) out[(size_t)v * 16 + c] = val - m - logf(ssum);
}

// ---------------- host ----------------
extern "C" void kernel_launch(void* const* d_in, const int* in_sizes, int n_in,
                              void* d_out, int out_size) {
    const float* x     = (const float*)d_in[0];
    const float* eattr = (const float*)d_in[1];
    const int*   src   = (const int*)  d_in[2];
    const int*   dst   = (const int*)  d_in[3];
    const float* W1 = (const float*)d_in[4];
    const float* R1 = (const float*)d_in[5];
    const float* b1 = (const float*)d_in[6];
    const float* Wa = (const float*)d_in[7];
    const float* Ra = (const float*)d_in[8];
    const float* ba = (const float*)d_in[9];
    const float* Wb = (const float*)d_in[10];
    const float* Rb = (const float*)d_in[11];
    const float* bb = (const float*)d_in[12];
    const float* W2 = (const float*)d_in[13];
    const float* R2 = (const float*)d_in[14];
    const float* b2 = (const float*)d_in[15];
    float* out = (float*)d_out;

    void *pZ, *ph, *py, *pt, *pk, *pka, *phf, *pG2, *pB1, *pBA, *pBB, *pB2;
    cudaGetSymbolAddress(&pZ,  g_Z);
    cudaGetSymbolAddress(&ph,  g_h);
    cudaGetSymbolAddress(&py,  g_y);
    cudaGetSymbolAddress(&pt,  g_t);
    cudaGetSymbolAddress(&pk,  g_k);
    cudaGetSymbolAddress(&pka, g_ka);
    cudaGetSymbolAddress(&phf, g_hf);
    cudaGetSymbolAddress(&pG2, g_G2);
    cudaGetSymbolAddress(&pB1, g_B1);
    cudaGetSymbolAddress(&pBA, g_BA);
    cudaGetSymbolAddress(&pBB, g_BB);
    cudaGetSymbolAddress(&pB2, g_B2);

    const int EDGE_GRID = (NN * 32 + 255) / 256;   // warp per node, 8 warps/block
    dim3 gemm1((NN + 127) / 128, 3);               // N=192
    dim3 gemmI((NN + 127) / 128, 1);               // N=64 or 48

    // CSR build
    k_zero<<<(NN + 255) / 256, 256>>>();
    k_hist<<<(NE + 255) / 256, 256>>>(dst);
    k_scan<<<1, 1024>>>();
    k_scatter<<<(NE + 255) / 256, 256>>>(src, dst, eattr);

    // weight prep
    k_prep_tf<<<(NF * 192 + 255) / 256, 256>>>(W1, R1, (float*)pB1, NF, NH);
    k_prep_af<<<(192 * NH + 255) / 256, 256>>>(Wa, Ra, (float*)pBA, NH);
    k_prep_af<<<(192 * NH + 255) / 256, 256>>>(Wb, Rb, (float*)pBB, NH);
    k_prep_tf<<<(NH * 48 + 255) / 256, 256>>>(W2, R2, (float*)pB2, NH, NC);

    // conv1: transform-first GEMM then edge pass (tanh)
    k_gemm<<<gemm1, 128>>>(x, (const float*)pB1, (float*)pZ, nullptr,
                           NN, NF, 192, 192, 0, nullptr, nullptr, nullptr, 0.f, 0.f, 0);
    k_edge1<<<EDGE_GRID, 256>>>(b1);

    // RK4: k1
    k_agg<<<EDGE_GRID, 256>>>((const float*)ph);
    k_gemm<<<gemmI, 128>>>((const float*)pZ, (const float*)pBA, (float*)pt, ba,
                           NN, 192, 64, 64, 0, nullptr, nullptr, nullptr, 0.f, 0.f, 0);
    k_agg<<<EDGE_GRID, 256>>>((const float*)pt);
    k_gemm<<<gemmI, 128>>>((const float*)pZ, (const float*)pBB, (float*)pk, bb,
                           NN, 192, 64, 64, 1, (const float*)ph, (float*)py, (float*)pka,
                           1.5f, 1.0f, 1);
    // k2
    k_agg<<<EDGE_GRID, 256>>>((const float*)py);
    k_gemm<<<gemmI, 128>>>((const float*)pZ, (const float*)pBA, (float*)pt, ba,
                           NN, 192, 64, 64, 0, nullptr, nullptr, nullptr, 0.f, 0.f, 0);
    k_agg<<<EDGE_GRID, 256>>>((const float*)pt);
    k_gemm<<<gemmI, 128>>>((const float*)pZ, (const float*)pBB, (float*)pk, bb,
                           NN, 192, 64, 64, 1, (const float*)ph, (float*)py, (float*)pka,
                           1.5f, 2.0f, 0);
    // k3
    k_agg<<<EDGE_GRID, 256>>>((const float*)py);
    k_gemm<<<gemmI, 128>>>((const float*)pZ, (const float*)pBA, (float*)pt, ba,
                           NN, 192, 64, 64, 0, nullptr, nullptr, nullptr, 0.f, 0.f, 0);
    k_agg<<<EDGE_GRID, 256>>>((const float*)pt);
    k_gemm<<<gemmI, 128>>>((const float*)pZ, (const float*)pBB, (float*)pk, bb,
                           NN, 192, 64, 64, 1, (const float*)ph, (float*)py, (float*)pka,
                           3.0f, 2.0f, 0);
    // k4
    k_agg<<<EDGE_GRID, 256>>>((const float*)py);
    k_gemm<<<gemmI, 128>>>((const float*)pZ, (const float*)pBA, (float*)pt, ba,
                           NN, 192, 64, 64, 0, nullptr, nullptr, nullptr, 0.f, 0.f, 0);
    k_agg<<<EDGE_GRID, 256>>>((const float*)pt);
    k_gemm<<<gemmI, 128>>>((const float*)pZ, (const float*)pBB, (float*)pk, bb,
                           NN, 192, 64, 64, 1, (const float*)ph, nullptr, (float*)pka,
                           0.f, 1.0f, 0);

    // hf = h + 0.5*kacc ; conv2 ; softmax
    k_comb<<<(NN * NH + 255) / 256, 256>>>();
    k_gemm<<<gemmI, 128>>>((const float*)phf, (const float*)pB2, (float*)pG2, nullptr,
                           NN, 64, 48, 48, 0, nullptr, nullptr, nullptr, 0.f, 0.f, 0);
    k_edge2<<<EDGE_GRID, 256>>>(b2, out);
}